// round 17
// baseline (speedup 1.0000x reference)
#include <cuda_runtime.h>
#include <cuda_fp16.h>
#include <cstdint>
#include <math.h>

#define T_TOK 4096
#define HDIM  2048
#define NEXP  16
#define FDIM  768
#define TOPK  4

#define BM    128
#define BN    256                       // B rows per tile
#define ROWB  144                       // 128B data + 16B pad per smem row
#define ATILE (128 * ROWB)              // A region size; B starts here
#define STG   (384 * ROWB)              // 55296 B per stage
#define NSTG  4
#define SMEM_GEMM (1024 + NSTG * STG)   // 222208 B -> 1 block/SM
#define REX   132                       // exchange row stride (floats, mult of 4)

#define NSM   152                       // GB300 SM count

// ticket-scavenged side work in gemm1 tail: Wd cvt + out zero
#define WD_F4    ((NEXP * HDIM * FDIM) / 4)       // 6291456
#define OUT_F4   ((T_TOK * HDIM) / 4)             // 2097152
#define CHUNK_F4 8192                             // 512 thr * 16 float4
#define NT_WD    (WD_F4 / CHUNK_F4)               // 768
#define NT_OUT   (OUT_F4 / CHUNK_F4)              // 256
#define NTICK    (NT_WD + NT_OUT)                 // 1024

// ---- scratch (device globals; allocation is forbidden) ----
__device__ int    g_counts[NEXP];
__device__ int    g_t1cum[NEXP + 1];
__device__ int    g_t2cum[NEXP + 1];
__device__ int    g_tile1, g_tile2, g_tick;
__device__ int    g_tok[NEXP * T_TOK];
__device__ float  g_w[NEXP * T_TOK];
__device__ __half g_x16[(size_t)T_TOK * HDIM];
__device__ __half g_wg16[(size_t)NEXP * FDIM * HDIM];
__device__ __half g_wu16[(size_t)NEXP * FDIM * HDIM];
__device__ __half g_wd16[(size_t)NEXP * HDIM * FDIM];
__device__ __half g_act16[(size_t)NEXP * T_TOK * FDIM];

// ---------------------------------------------------------------------------
// helpers
// ---------------------------------------------------------------------------
__device__ __forceinline__ uint32_t smem_u32(const void* p) {
    uint32_t a;
    asm("{ .reg .u64 t; cvta.to.shared.u64 t, %1; cvt.u32.u64 %0, t; }" : "=r"(a) : "l"(p));
    return a;
}
__device__ __forceinline__ void cp16(uint32_t smem, const void* g) {
    asm volatile("cp.async.cg.shared.global [%0], [%1], 16;" :: "r"(smem), "l"(g));
}
__device__ __forceinline__ void cp_commit() { asm volatile("cp.async.commit_group;"); }
template <int N>
__device__ __forceinline__ void cp_wait() { asm volatile("cp.async.wait_group %0;" :: "n"(N)); }

#define MMA_F16(C, A0, A1, A2, A3, B0, B1) \
    asm volatile("mma.sync.aligned.m16n8k16.row.col.f32.f16.f16.f32 " \
                 "{%0,%1,%2,%3}, {%4,%5,%6,%7}, {%8,%9}, {%0,%1,%2,%3};" \
                 : "+f"((C)[0]), "+f"((C)[1]), "+f"((C)[2]), "+f"((C)[3]) \
                 : "r"(A0), "r"(A1), "r"(A2), "r"(A3), "r"(B0), "r"(B1))

#define LDSM4(R, addr) \
    asm volatile("ldmatrix.sync.aligned.m8n8.x4.shared.b16 {%0,%1,%2,%3}, [%4];" \
                 : "=r"((R)[0]), "=r"((R)[1]), "=r"((R)[2]), "=r"((R)[3]) : "r"(addr))

__device__ __forceinline__ void cvt_store4(const float4 v, __half* dst) {
    __half2 a = __floats2half2_rn(v.x, v.y);
    __half2 b = __floats2half2_rn(v.z, v.w);
    uint2 u = make_uint2(*(const uint32_t*)&a, *(const uint32_t*)&b);
    *(uint2*)dst = u;
}

// ---------------------------------------------------------------------------
// prep: fp32 -> fp16 for Wg/Wu only; zero counts. (Wd + out handled in
// gemm1's tail ticket loop.)
// ---------------------------------------------------------------------------
__global__ void prep_kernel(const float4* __restrict__ Wg,
                            const float4* __restrict__ Wu) {
    size_t i0 = (size_t)blockIdx.x * blockDim.x + threadIdx.x;
    size_t st = (size_t)gridDim.x * blockDim.x;
    const size_t nw4 = (size_t)NEXP * FDIM * HDIM / 4;
    for (size_t i = i0; i < nw4; i += st) {
        cvt_store4(Wg[i], g_wg16 + 4 * i);
        cvt_store4(Wu[i], g_wu16 + 4 * i);
    }
    if (i0 < NEXP) g_counts[i0] = 0;
}

// ---------------------------------------------------------------------------
// Router: 16 tokens/block; emits fp16 x copy; appends directly to the
// per-expert compacted lists (dispatch merged in).
// ---------------------------------------------------------------------------
#define RT_TOKS 16
#define RT_PAD  2052
#define RT_SMEM ((RT_TOKS * RT_PAD + RT_TOKS * NEXP) * 4)

__global__ __launch_bounds__(256) void router_kernel(const float* __restrict__ x,
                                                     const float* __restrict__ Wr) {
    extern __shared__ float rs[];
    float* xs = rs;
    float* lg = rs + RT_TOKS * RT_PAD;
    int tid = threadIdx.x;
    int tok0 = blockIdx.x * RT_TOKS;

    for (int idx = tid; idx < RT_TOKS * HDIM; idx += 256) {
        int t = idx >> 11, k = idx & (HDIM - 1);
        xs[t * RT_PAD + k] = x[(size_t)(tok0 + t) * HDIM + k];
    }
    __syncthreads();

    for (int idx = tid * 4; idx < RT_TOKS * HDIM; idx += 256 * 4) {
        int t = idx >> 11, k = idx & (HDIM - 1);
        float4 v = *(const float4*)(xs + t * RT_PAD + k);
        cvt_store4(v, g_x16 + (size_t)(tok0 + t) * HDIM + k);
    }

    int t = tid & 15, e = tid >> 4;
    const float* wr = Wr + (size_t)e * HDIM;
    const float* xr = xs + t * RT_PAD;
    float acc = 0.0f;
#pragma unroll 8
    for (int k = 0; k < HDIM; k++) acc += xr[k] * wr[k];
    lg[t * NEXP + e] = acc;
    __syncthreads();

    if (tid < RT_TOKS) {
        int tt = tok0 + tid;
        const float* l = lg + tid * NEXP;
        float m = l[0];
#pragma unroll
        for (int i = 1; i < NEXP; i++) m = fmaxf(m, l[i]);
        float p[NEXP]; float s = 0.0f;
#pragma unroll
        for (int i = 0; i < NEXP; i++) { p[i] = expf(l[i] - m); s += p[i]; }
        float inv_s = 1.0f / s;
        bool used[NEXP];
#pragma unroll
        for (int i = 0; i < NEXP; i++) used[i] = false;
        int ids[TOPK]; float ws[TOPK]; float wsum = 0.0f;
#pragma unroll
        for (int k = 0; k < TOPK; k++) {
            int bi = -1; float bv = -1.0f;
#pragma unroll
            for (int i = 0; i < NEXP; i++)
                if (!used[i] && p[i] > bv) { bv = p[i]; bi = i; }
            used[bi] = true;
            ids[k] = bi; ws[k] = bv * inv_s; wsum += ws[k];
        }
        float inv_w = 1.0f / wsum;
#pragma unroll
        for (int k = 0; k < TOPK; k++) {
            int ee = ids[k];
            int pos = atomicAdd(&g_counts[ee], 1);
            g_tok[ee * T_TOK + pos] = tt;
            g_w[ee * T_TOK + pos]   = ws[k] * inv_w;
        }
    }
}

// ---------------------------------------------------------------------------
// plan: cumulative tile tables for both persistent GEMMs; reset counters.
// ---------------------------------------------------------------------------
__global__ void plan_kernel() {
    if (threadIdx.x == 0) {
        int c1 = 0, c2 = 0;
        for (int e = 0; e < NEXP; e++) {
            g_t1cum[e] = c1;
            g_t2cum[e] = c2;
            int mb = (g_counts[e] + BM - 1) / BM;
            c1 += mb * (FDIM / 128);    // 6 n-tiles
            c2 += mb * (HDIM / BN);     // 8 n-tiles
        }
        g_t1cum[NEXP] = c1;
        g_t2cum[NEXP] = c2;
        g_tile1 = 0; g_tile2 = 0; g_tick = 0;
    }
}

// ---------------------------------------------------------------------------
// Ticket drain (gemm1 tail only): Wd f32->fp16 + out zeroing.
// ---------------------------------------------------------------------------
__device__ __forceinline__ void drain_tickets(const float4* __restrict__ Wd,
                                              float4* __restrict__ out,
                                              int tid) {
    __shared__ int tk;
    for (;;) {
        __syncthreads();
        if (tid == 0) tk = atomicAdd(&g_tick, 1);
        __syncthreads();
        int t = tk;
        if (t >= NTICK) return;
        if (t < NT_WD) {
            size_t base = (size_t)t * CHUNK_F4 + tid * 16;
#pragma unroll 4
            for (int j = 0; j < 16; j++)
                cvt_store4(Wd[base + j], g_wd16 + 4 * (base + j));
        } else {
            size_t base = (size_t)(t - NT_WD) * CHUNK_F4 + tid * 16;
            const float4 z = make_float4(0.f, 0.f, 0.f, 0.f);
#pragma unroll 4
            for (int j = 0; j < 16; j++)
                out[base + j] = z;
        }
    }
}

// ---------------------------------------------------------------------------
// Mainloop: BM=128, BN=256, BK=64 halves. 512 threads, 16 warps of 32x64.
// 4-stage cp.async ring; issue(it+2) -> commit -> wait<2> -> barrier ->
// compute(it). Unchanged from the round-15 win.
// ---------------------------------------------------------------------------
struct Frag { float acc[2][8][4]; };

__device__ __forceinline__ void mainloop(uint32_t sb1,
                                         const char* asrc0, const char* asrc1,
                                         const char* bsrc0, const char* bsrc1,
                                         uint32_t RS, uint32_t dstb, int NIT,
                                         int wm, int wc, int lane, Frag& F) {
    auto issue = [&](int s, int kb) {
        uint32_t d0 = sb1 + s * STG + dstb;
        cp16(d0,              asrc0 + kb);
        cp16(d0 +  64 * ROWB, asrc1 + kb);
        cp16(d0 + 128 * ROWB, bsrc0 + kb);
        cp16(d0 + 192 * ROWB, bsrc0 + 64 * RS + kb);
        cp16(d0 + 256 * ROWB, bsrc1 + kb);
        cp16(d0 + 320 * ROWB, bsrc1 + 64 * RS + kb);
    };

    uint32_t a_lane = (uint32_t)((lane & 15) * ROWB + (lane >> 4) * 16);
    uint32_t b_lane = (uint32_t)(((lane >> 4) * 8 + (lane & 7)) * ROWB + ((lane >> 3) & 1) * 16);
    uint32_t aoff0 = (uint32_t)(wm * 32 * ROWB) + a_lane;
    uint32_t aoff1 = aoff0 + 16 * ROWB;
    uint32_t boff  = ATILE + (uint32_t)(wc * 64 * ROWB) + b_lane;

    issue(0, 0);   cp_commit();
    issue(1, 128); cp_commit();

    for (int it = 0; it < NIT; ++it) {
        int pf = it + 2;
        if (pf < NIT) issue(pf & 3, pf * 128);
        cp_commit();
        cp_wait<2>();
        __syncthreads();

        uint32_t base = sb1 + (it & 3) * STG;
#pragma unroll
        for (int ks = 0; ks < 4; ks++) {
            uint32_t ko = ks * 32;
            uint32_t a0[4], a1[4];
            LDSM4(a0, base + aoff0 + ko);
            LDSM4(a1, base + aoff1 + ko);
#pragma unroll
            for (int np = 0; np < 4; np++) {
                uint32_t b[4];
                LDSM4(b, base + boff + np * (16 * ROWB) + ko);
                MMA_F16(F.acc[0][2 * np],     a0[0], a0[1], a0[2], a0[3], b[0], b[1]);
                MMA_F16(F.acc[0][2 * np + 1], a0[0], a0[1], a0[2], a0[3], b[2], b[3]);
                MMA_F16(F.acc[1][2 * np],     a1[0], a1[1], a1[2], a1[3], b[0], b[1]);
                MMA_F16(F.acc[1][2 * np + 1], a1[0], a1[1], a1[2], a1[3], b[2], b[3]);
            }
        }
    }
    // drain remaining groups so next tile's prologue can't collide
    cp_wait<0>();
}

// ---------------------------------------------------------------------------
// GEMM1 (persistent): tiles from g_tile1; after queue empty, drain Wd/out
// tickets in the tail bubble. grid (NSM), 512 threads.
// ---------------------------------------------------------------------------
__global__ __launch_bounds__(512, 1) void gemm1_kernel(const float4* __restrict__ Wd,
                                                       float4* __restrict__ out) {
    extern __shared__ char smem[];
    __shared__ int s_tile;
    int tid = threadIdx.x;
    uint32_t sb1 = smem_u32(smem) + 1024;
    int wid = tid >> 5, lane = tid & 31;
    int wm = wid & 3, wc = wid >> 2;          // wc 0,1 = gate; 2,3 = up
    int r = tid >> 3, c = tid & 7;
    int qr = lane >> 2, qc = lane & 3;
    int* toks = (int*)smem;

    for (;;) {
        __syncthreads();
        if (tid == 0) s_tile = atomicAdd(&g_tile1, 1);
        __syncthreads();
        int t = s_tile;
        if (t >= g_t1cum[NEXP]) break;

        int e = 0;
        while (g_t1cum[e + 1] <= t) e++;
        int lt = t - g_t1cum[e];
        int m0 = (lt / (FDIM / 128)) * BM;
        int n0 = (lt % (FDIM / 128)) * 128;
        int cnt = g_counts[e];

        if (tid < BM) {
            int m = m0 + tid;
            toks[tid] = (m < cnt) ? g_tok[e * T_TOK + m] : g_tok[e * T_TOK];
        }
        __syncthreads();

        const char* asrc0 = (const char*)(g_x16 + (size_t)toks[r] * HDIM) + c * 16;
        const char* asrc1 = (const char*)(g_x16 + (size_t)toks[r + 64] * HDIM) + c * 16;
        const char* bsrc0 = (const char*)(g_wg16 + ((size_t)e * FDIM + n0 + r) * HDIM) + c * 16;
        const char* bsrc1 = (const char*)(g_wu16 + ((size_t)e * FDIM + n0 + r) * HDIM) + c * 16;
        uint32_t dstb = (uint32_t)(r * ROWB + c * 16);

        Frag F = {};
        mainloop(sb1, asrc0, asrc1, bsrc0, bsrc1, HDIM * 2, dstb,
                 HDIM * 2 / 128, wm, wc, lane, F);

        // exchange gate/up halves, SiLU combine, store fp16 act
        __syncthreads();
        float* ex = (float*)(smem + 1024);
        float* eu = ex + 128 * REX;
        float* dbuf = (wc < 2) ? ex : eu;
        int cb0 = (wc & 1) * 64;
#pragma unroll
        for (int mi = 0; mi < 2; mi++) {
            int rr = wm * 32 + mi * 16 + qr;
#pragma unroll
            for (int ni = 0; ni < 8; ni++) {
                int col = cb0 + ni * 8 + qc * 2;
                *(float2*)&dbuf[rr * REX + col]       = make_float2(F.acc[mi][ni][0], F.acc[mi][ni][1]);
                *(float2*)&dbuf[(rr + 8) * REX + col] = make_float2(F.acc[mi][ni][2], F.acc[mi][ni][3]);
            }
        }
        __syncthreads();

        int rr = tid >> 2, cb = (tid & 3) * 32;
        int m = m0 + rr;
        if (m < cnt) {
            float rw = g_w[e * T_TOK + m];
            __half* dst = g_act16 + ((size_t)e * T_TOK + m) * FDIM + n0 + cb;
            const float* gg = ex + rr * REX + cb;
            const float* uu = eu + rr * REX + cb;
#pragma unroll
            for (int j = 0; j < 32; j += 4) {
                float4 g4 = *(const float4*)(gg + j);
                float4 u4 = *(const float4*)(uu + j);
                float4 v;
                v.x = g4.x / (1.0f + expf(-g4.x)) * u4.x * rw;
                v.y = g4.y / (1.0f + expf(-g4.y)) * u4.y * rw;
                v.z = g4.z / (1.0f + expf(-g4.z)) * u4.z * rw;
                v.w = g4.w / (1.0f + expf(-g4.w)) * u4.w * rw;
                cvt_store4(v, dst + j);
            }
        }
    }

    drain_tickets(Wd, out, tid);   // tail bubble: Wd cvt + out zero
}

// ---------------------------------------------------------------------------
// GEMM2 (persistent): out[tok] += act16 @ Wd16^T, BN=256, K=768.
// grid (NSM), 512 threads.
// ---------------------------------------------------------------------------
__global__ __launch_bounds__(512, 1) void gemm2_kernel(float* __restrict__ out) {
    extern __shared__ char smem[];
    __shared__ int s_tile;
    int tid = threadIdx.x;
    uint32_t sb1 = smem_u32(smem) + 1024;
    int wid = tid >> 5, lane = tid & 31;
    int wm = wid & 3, wn = wid >> 2;
    int r = tid >> 3, c = tid & 7;
    int qr = lane >> 2, qc = lane & 3;
    int* toks = (int*)smem;

    for (;;) {
        __syncthreads();
        if (tid == 0) s_tile = atomicAdd(&g_tile2, 1);
        __syncthreads();
        int t = s_tile;
        if (t >= g_t2cum[NEXP]) break;

        int e = 0;
        while (g_t2cum[e + 1] <= t) e++;
        int lt = t - g_t2cum[e];
        int m0 = (lt / (HDIM / BN)) * BM;
        int n0 = (lt % (HDIM / BN)) * BN;
        int cnt = g_counts[e];

        if (tid < BM) {
            int m = m0 + tid;
            toks[tid] = (m < cnt) ? g_tok[e * T_TOK + m] : g_tok[e * T_TOK];
        }
        __syncthreads();

        const char* asrc0 = (const char*)(g_act16 + ((size_t)e * T_TOK + m0 + r) * FDIM) + c * 16;
        const char* asrc1 = asrc0 + (size_t)64 * FDIM * 2;
        const char* bsrc0 = (const char*)(g_wd16 + ((size_t)e * HDIM + n0 + r) * FDIM) + c * 16;
        const char* bsrc1 = bsrc0 + (size_t)128 * FDIM * 2;
        uint32_t dstb = (uint32_t)(r * ROWB + c * 16);

        Frag F = {};
        mainloop(sb1, asrc0, asrc1, bsrc0, bsrc1, FDIM * 2, dstb,
                 FDIM * 2 / 128, wm, wn, lane, F);

        // scatter-add epilogue (f32x2 RED)
#pragma unroll
        for (int mi = 0; mi < 2; mi++) {
#pragma unroll
            for (int rh = 0; rh < 2; rh++) {
                int mrow = wm * 32 + mi * 16 + rh * 8 + qr;
                int m = m0 + mrow;
                if (m < cnt) {
                    float* dst = out + (size_t)toks[mrow] * HDIM + n0 + wn * 64;
#pragma unroll
                    for (int ni = 0; ni < 8; ni++) {
                        float2 v = make_float2(F.acc[mi][ni][rh * 2 + 0], F.acc[mi][ni][rh * 2 + 1]);
                        atomicAdd(reinterpret_cast<float2*>(dst + ni * 8 + qc * 2), v);
                    }
                }
            }
        }
    }
}

// ---------------------------------------------------------------------------
extern "C" void kernel_launch(void* const* d_in, const int* in_sizes, int n_in,
                              void* d_out, int out_size) {
    const float* x  = (const float*)d_in[0];
    const float* Wr = (const float*)d_in[1];
    const float* Wg = (const float*)d_in[2];
    const float* Wu = (const float*)d_in[3];
    const float* Wd = (const float*)d_in[4];
    float* out = (float*)d_out;

    cudaFuncSetAttribute(router_kernel, cudaFuncAttributeMaxDynamicSharedMemorySize, RT_SMEM);
    cudaFuncSetAttribute(gemm1_kernel,  cudaFuncAttributeMaxDynamicSharedMemorySize, SMEM_GEMM);
    cudaFuncSetAttribute(gemm2_kernel,  cudaFuncAttributeMaxDynamicSharedMemorySize, SMEM_GEMM);

    prep_kernel<<<1024, 256>>>((const float4*)Wg, (const float4*)Wu);

    router_kernel<<<T_TOK / RT_TOKS, 256, RT_SMEM>>>(x, Wr);

    plan_kernel<<<1, 32>>>();

    gemm1_kernel<<<NSM, 512, SMEM_GEMM>>>((const float4*)Wd, (float4*)out);

    gemm2_kernel<<<NSM, 512, SMEM_GEMM>>>(out);
}